// round 13
// baseline (speedup 1.0000x reference)
#include <cuda_runtime.h>
#include <cstdint>
#include <cstddef>

#define B_ 256
#define T_ 2048
#define I_ 128
#define H_ 64
#define G_ 256          // 4*H
#define M_ (B_*T_)      // 524288

// Scratch (device globals: allocation-free rule)
__device__ float g_pre[(size_t)M_ * G_];   // 512 MB
__device__ float g_h0 [(size_t)M_ * H_];   // 128 MB
__device__ float g_h1 [(size_t)M_ * H_];   // 128 MB

// ---------------------------------------------------------------- helpers
__device__ __forceinline__ void mma_tf32(float c[4], const unsigned a[4],
                                         unsigned b0, unsigned b1){
    asm volatile("mma.sync.aligned.m16n8k8.row.col.f32.tf32.tf32.f32 "
        "{%0,%1,%2,%3},{%4,%5,%6,%7},{%8,%9},{%0,%1,%2,%3};"
        : "+f"(c[0]),"+f"(c[1]),"+f"(c[2]),"+f"(c[3])
        : "r"(a[0]),"r"(a[1]),"r"(a[2]),"r"(a[3]),"r"(b0),"r"(b1));
}

__device__ __forceinline__ float tanh_fast(float x){
    float y; asm("tanh.approx.f32 %0, %1;" : "=f"(y) : "f"(x)); return y;
}

__device__ __forceinline__ unsigned smaddr(const void* p){
    return (unsigned)__cvta_generic_to_shared(p);
}
__device__ __forceinline__ void cp16(unsigned dst, const void* src){
    asm volatile("cp.async.cg.shared.global [%0], [%1], 16;" :: "r"(dst), "l"(src));
}

// ---------------------------------------------------------------- pre-GEMM
// (R8 exact) 512 threads, BM=128, N=256, K chunked 32, cp.async dbl buffer.
#define KC 32
#define KP 36
#define STAGE_F (128*KP + 256*KP)

template<int K>
__global__ void __launch_bounds__(512,1)
gemm_pre(const float* __restrict__ A, const float* __restrict__ W,
         const float* __restrict__ b_ih, const float* __restrict__ b_hh,
         float* __restrict__ out)
{
    extern __shared__ float sm[];
    float* bs = sm + 2*STAGE_F;

    const int tid = threadIdx.x;
    const size_t m0 = (size_t)blockIdx.x * 128;

    if (tid < 256) bs[tid] = b_ih[tid] + b_hh[tid];

    auto copy_chunk = [&](int c, int st){
        float* Asd = sm + st*STAGE_F;
        float* Wsd = Asd + 128*KP;
        #pragma unroll
        for (int i = tid; i < 128*8; i += 512){
            int row = i >> 3, seg = i & 7;
            cp16(smaddr(Asd + row*KP + seg*4),
                 A + (m0 + row)*(size_t)K + c*KC + seg*4);
        }
        #pragma unroll
        for (int i = tid; i < 256*8; i += 512){
            int row = i >> 3, seg = i & 7;
            cp16(smaddr(Wsd + row*KP + seg*4),
                 W + (size_t)row*K + c*KC + seg*4);
        }
    };

    const int warp = tid >> 5, lane = tid & 31;
    const int wm = warp >> 2, wn = warp & 3;
    const int gid = lane >> 2, tig = lane & 3;

    float acc[2][8][4];
    #pragma unroll
    for (int a = 0; a < 2; a++)
        #pragma unroll
        for (int b = 0; b < 8; b++)
            #pragma unroll
            for (int d = 0; d < 4; d++) acc[a][b][d] = 0.f;

    constexpr int NCH = K / KC;

    copy_chunk(0, 0);
    asm volatile("cp.async.commit_group;");

    for (int c = 0; c < NCH; ++c){
        if (c + 1 < NCH){
            copy_chunk(c + 1, (c + 1) & 1);
            asm volatile("cp.async.commit_group;");
            asm volatile("cp.async.wait_group 1;");
        } else {
            asm volatile("cp.async.wait_group 0;");
        }
        __syncthreads();

        const float* As = sm + (c & 1)*STAGE_F;
        const float* Ws = As + 128*KP;

        #pragma unroll
        for (int ks = 0; ks < KC/8; ++ks){
            const int cc = ks*8 + tig;
            unsigned af[2][4];
            #pragma unroll
            for (int mt = 0; mt < 2; mt++){
                int r = wm*32 + mt*16 + gid;
                af[mt][0] = __float_as_uint(As[r*KP + cc]);
                af[mt][1] = __float_as_uint(As[(r+8)*KP + cc]);
                af[mt][2] = __float_as_uint(As[r*KP + cc + 4]);
                af[mt][3] = __float_as_uint(As[(r+8)*KP + cc + 4]);
            }
            #pragma unroll
            for (int nt = 0; nt < 8; nt++){
                int n = wn*64 + nt*8 + gid;
                unsigned b0 = __float_as_uint(Ws[n*KP + cc]);
                unsigned b1 = __float_as_uint(Ws[n*KP + cc + 4]);
                mma_tf32(acc[0][nt], af[0], b0, b1);
                mma_tf32(acc[1][nt], af[1], b0, b1);
            }
        }
        __syncthreads();
    }

    #pragma unroll
    for (int mt = 0; mt < 2; mt++){
        size_t r = m0 + wm*32 + mt*16 + gid;
        #pragma unroll
        for (int nt = 0; nt < 8; nt++){
            int col = wn*64 + nt*8 + 2*tig;
            float bb0 = bs[col], bb1 = bs[col+1];
            *(float2*)(out + r*G_ + col)
                = make_float2(acc[mt][nt][0] + bb0, acc[mt][nt][1] + bb1);
            *(float2*)(out + (r+8)*G_ + col)
                = make_float2(acc[mt][nt][2] + bb0, acc[mt][nt][3] + bb1);
        }
    }
}

// ---------------------------------------------------------------- LSTM scan
// TENSOR-CORE scan, gate-type-per-N-tile mapping. Block = 8 seqs, 256 thr.
// Warp w's 4 N-tiles are gates nsub*64 + w*8 + (0..7) with nsub = GATE TYPE
// (0=i,1=f,2=g,3=o). After mma, C-thread (gid,tig) holds i,f,g,o of cells
// w*8+2tig,+1 for seq gid entirely in registers -> cell update is local,
// cell state is register-resident, NO act smem, ONE barrier/step. K-chain
// split 2x4 mmas (8 independent chains). pre via cp.async double buffer.
#define SQ 8                      // sequences per block
#define PRP 264                   // padded row (floats) for pre
#define HRP 68                    // padded row for h (conflict-free frags)

__global__ void __launch_bounds__(256,1)
lstm_scan(const float* __restrict__ pre, const float* __restrict__ w_hh,
          float* __restrict__ h_out)
{
    __shared__ __align__(16) float pre_s[2][SQ][PRP];
    __shared__ __align__(16) float h_s[2][SQ][HRP];

    const int tid  = threadIdx.x;
    const int warp = tid >> 5, lane = tid & 31;
    const int gid  = lane >> 2, tig = lane & 3;
    const int sbase = blockIdx.x * SQ;

    for (int i = tid; i < 2*SQ*HRP; i += 256) ((float*)h_s)[i] = 0.f;

    // B-fragments: nsub = gate type; gate = nsub*64 + warp*8 + gid
    unsigned bw[4][8][2];
    #pragma unroll
    for (int nsub = 0; nsub < 4; nsub++){
        int gate = nsub*64 + warp*8 + gid;
        #pragma unroll
        for (int ks = 0; ks < 8; ks++){
            bw[nsub][ks][0] = __float_as_uint(w_hh[gate*H_ + ks*8 + tig]);
            bw[nsub][ks][1] = __float_as_uint(w_hh[gate*H_ + ks*8 + tig + 4]);
        }
    }

    // cp.async staging of pre: 8 seq x 256 floats = 512 cp16
    auto stage_pre = [&](int t, int buf){
        #pragma unroll
        for (int r = 0; r < 2; r++){
            int idx = tid + r*256;
            int seq = idx >> 6, seg = idx & 63;
            cp16(smaddr(&pre_s[buf][seq][seg*4]),
                 pre + ((size_t)(sbase + seq)*T_ + t)*G_ + seg*4);
        }
    };

    stage_pre(0, 0);
    asm volatile("cp.async.commit_group;");
    stage_pre(1, 1);
    asm volatile("cp.async.commit_group;");

    // cell state: this thread owns seq gid, cells warp*8+2tig, +1
    float c0 = 0.f, c1 = 0.f;
    const int jc = warp*8 + 2*tig;

    __syncthreads();

    for (int t = 0; t < T_; ++t){
        const int rb = t & 1;

        // gates = h @ W^T : 4 gate types x (2 chains of 4 mma)
        float C[4][4], D[4][4];
        #pragma unroll
        for (int n = 0; n < 4; n++)
            #pragma unroll
            for (int d = 0; d < 4; d++){ C[n][d] = 0.f; D[n][d] = 0.f; }

        #pragma unroll
        for (int ks = 0; ks < 4; ks++){
            unsigned a0[4], a1[4];
            a0[0] = __float_as_uint(h_s[rb][gid][ks*8 + tig]);
            a0[1] = 0u;
            a0[2] = __float_as_uint(h_s[rb][gid][ks*8 + tig + 4]);
            a0[3] = 0u;
            a1[0] = __float_as_uint(h_s[rb][gid][32 + ks*8 + tig]);
            a1[1] = 0u;
            a1[2] = __float_as_uint(h_s[rb][gid][32 + ks*8 + tig + 4]);
            a1[3] = 0u;
            #pragma unroll
            for (int nsub = 0; nsub < 4; nsub++){
                mma_tf32(C[nsub], a0, bw[nsub][ks][0],   bw[nsub][ks][1]);
                mma_tf32(D[nsub], a1, bw[nsub][ks+4][0], bw[nsub][ks+4][1]);
            }
        }

        // ensure pre[t] landed
        asm volatile("cp.async.wait_group 1;");

        // add pre, activate (nsub compile-time: 2 => tanh else sigmoid)
        float vv[4][2];
        #pragma unroll
        for (int nsub = 0; nsub < 4; nsub++){
            float2 p = *(const float2*)&pre_s[rb][gid][nsub*64 + jc];
            float x0 = C[nsub][0] + D[nsub][0] + p.x;
            float x1 = C[nsub][1] + D[nsub][1] + p.y;
            if (nsub == 2){
                vv[nsub][0] = tanh_fast(x0);
                vv[nsub][1] = tanh_fast(x1);
            } else {
                vv[nsub][0] = fmaf(tanh_fast(0.5f*x0), 0.5f, 0.5f);
                vv[nsub][1] = fmaf(tanh_fast(0.5f*x1), 0.5f, 0.5f);
            }
        }

        // cell update — fully register-local
        c0 = fmaf(vv[1][0], c0, vv[0][0] * vv[2][0]);
        c1 = fmaf(vv[1][1], c1, vv[0][1] * vv[2][1]);
        float h0v = vv[3][0] * tanh_fast(c0);
        float h1v = vv[3][1] * tanh_fast(c1);

        *(float2*)&h_s[rb ^ 1][gid][jc] = make_float2(h0v, h1v);
        *(float2*)(h_out + ((size_t)(sbase + gid)*T_ + t)*H_ + jc)
            = make_float2(h0v, h1v);

        __syncthreads();      // publish h(t+1); pre_s[rb] fully consumed

        // refill pre buffer rb with pre[t+2]
        int tc = (t + 2 < T_) ? t + 2 : T_ - 1;
        stage_pre(tc, rb);
        asm volatile("cp.async.commit_group;");
    }
}

// ---------------------------------------------------------------- FC head
__global__ void fc_kernel(const float* __restrict__ h, const float* __restrict__ fw,
                          const float* __restrict__ fb, float* __restrict__ out)
{
    size_t m = (size_t)blockIdx.x * blockDim.x + threadIdx.x;
    const float4* hv = (const float4*)(h + m * H_);
    float acc = 0.f;
    #pragma unroll
    for (int i = 0; i < H_/4; i++){
        float4 a = hv[i];
        float4 w = __ldg(((const float4*)fw) + i);
        acc = fmaf(a.x, w.x, fmaf(a.y, w.y, fmaf(a.z, w.z, fmaf(a.w, w.w, acc))));
    }
    out[m] = acc + __ldg(fb);
}

// ---------------------------------------------------------------- launch
extern "C" void kernel_launch(void* const* d_in, const int* in_sizes, int n_in,
                              void* d_out, int out_size)
{
    const float* x     = (const float*)d_in[0];
    const float* w_ih0 = (const float*)d_in[1];
    const float* w_hh0 = (const float*)d_in[2];
    const float* b_ih0 = (const float*)d_in[3];
    const float* b_hh0 = (const float*)d_in[4];
    const float* w_ih1 = (const float*)d_in[5];
    const float* w_hh1 = (const float*)d_in[6];
    const float* b_ih1 = (const float*)d_in[7];
    const float* b_hh1 = (const float*)d_in[8];
    const float* w_ih2 = (const float*)d_in[9];
    const float* w_hh2 = (const float*)d_in[10];
    const float* b_ih2 = (const float*)d_in[11];
    const float* b_hh2 = (const float*)d_in[12];
    const float* fc_w  = (const float*)d_in[13];
    const float* fc_b  = (const float*)d_in[14];
    float* out = (float*)d_out;

    float *pre, *h0, *h1;
    cudaGetSymbolAddress((void**)&pre, g_pre);
    cudaGetSymbolAddress((void**)&h0,  g_h0);
    cudaGetSymbolAddress((void**)&h1,  g_h1);

    const int smemG = (2*STAGE_F + 256) * 4;
    cudaFuncSetAttribute(gemm_pre<128>, cudaFuncAttributeMaxDynamicSharedMemorySize, smemG);
    cudaFuncSetAttribute(gemm_pre<64>,  cudaFuncAttributeMaxDynamicSharedMemorySize, smemG);

    gemm_pre<128><<<M_/128, 512, smemG>>>(x,  w_ih0, b_ih0, b_hh0, pre);
    lstm_scan    <<<B_/SQ,  256>>>(pre, w_hh0, h0);
    gemm_pre<64> <<<M_/128, 512, smemG>>>(h0, w_ih1, b_ih1, b_hh1, pre);
    lstm_scan    <<<B_/SQ,  256>>>(pre, w_hh1, h1);
    gemm_pre<64> <<<M_/128, 512, smemG>>>(h1, w_ih2, b_ih2, b_hh2, pre);
    lstm_scan    <<<B_/SQ,  256>>>(pre, w_hh2, h0);
    fc_kernel    <<<M_/256, 256>>>(h0, fc_w, fc_b, out);
}

// round 14
// speedup vs baseline: 1.0236x; 1.0236x over previous
#include <cuda_runtime.h>
#include <cstdint>
#include <cstddef>

#define B_ 256
#define T_ 2048
#define I_ 128
#define H_ 64
#define G_ 256          // 4*H
#define M_ (B_*T_)      // 524288

// Scratch (device globals: allocation-free rule)
__device__ float g_pre[(size_t)M_ * G_];   // 512 MB
__device__ float g_h0 [(size_t)M_ * H_];   // 128 MB
__device__ float g_h1 [(size_t)M_ * H_];   // 128 MB

// ---------------------------------------------------------------- helpers
__device__ __forceinline__ void mma_tf32(float c[4], const unsigned a[4],
                                         unsigned b0, unsigned b1){
    asm volatile("mma.sync.aligned.m16n8k8.row.col.f32.tf32.tf32.f32 "
        "{%0,%1,%2,%3},{%4,%5,%6,%7},{%8,%9},{%0,%1,%2,%3};"
        : "+f"(c[0]),"+f"(c[1]),"+f"(c[2]),"+f"(c[3])
        : "r"(a[0]),"r"(a[1]),"r"(a[2]),"r"(a[3]),"r"(b0),"r"(b1));
}

__device__ __forceinline__ float tanh_fast(float x){
    float y; asm("tanh.approx.f32 %0, %1;" : "=f"(y) : "f"(x)); return y;
}

__device__ __forceinline__ unsigned smaddr(const void* p){
    return (unsigned)__cvta_generic_to_shared(p);
}
__device__ __forceinline__ void cp16(unsigned dst, const void* src){
    asm volatile("cp.async.cg.shared.global [%0], [%1], 16;" :: "r"(dst), "l"(src));
}

// ---------------------------------------------------------------- pre-GEMM
// (R8 exact) 512 threads, BM=128, N=256, K chunked 32, cp.async dbl buffer.
#define KC 32
#define KP 36
#define STAGE_F (128*KP + 256*KP)

template<int K>
__global__ void __launch_bounds__(512,1)
gemm_pre(const float* __restrict__ A, const float* __restrict__ W,
         const float* __restrict__ b_ih, const float* __restrict__ b_hh,
         float* __restrict__ out)
{
    extern __shared__ float sm[];
    float* bs = sm + 2*STAGE_F;

    const int tid = threadIdx.x;
    const size_t m0 = (size_t)blockIdx.x * 128;

    if (tid < 256) bs[tid] = b_ih[tid] + b_hh[tid];

    auto copy_chunk = [&](int c, int st){
        float* Asd = sm + st*STAGE_F;
        float* Wsd = Asd + 128*KP;
        #pragma unroll
        for (int i = tid; i < 128*8; i += 512){
            int row = i >> 3, seg = i & 7;
            cp16(smaddr(Asd + row*KP + seg*4),
                 A + (m0 + row)*(size_t)K + c*KC + seg*4);
        }
        #pragma unroll
        for (int i = tid; i < 256*8; i += 512){
            int row = i >> 3, seg = i & 7;
            cp16(smaddr(Wsd + row*KP + seg*4),
                 W + (size_t)row*K + c*KC + seg*4);
        }
    };

    const int warp = tid >> 5, lane = tid & 31;
    const int wm = warp >> 2, wn = warp & 3;
    const int gid = lane >> 2, tig = lane & 3;

    float acc[2][8][4];
    #pragma unroll
    for (int a = 0; a < 2; a++)
        #pragma unroll
        for (int b = 0; b < 8; b++)
            #pragma unroll
            for (int d = 0; d < 4; d++) acc[a][b][d] = 0.f;

    constexpr int NCH = K / KC;

    copy_chunk(0, 0);
    asm volatile("cp.async.commit_group;");

    for (int c = 0; c < NCH; ++c){
        if (c + 1 < NCH){
            copy_chunk(c + 1, (c + 1) & 1);
            asm volatile("cp.async.commit_group;");
            asm volatile("cp.async.wait_group 1;");
        } else {
            asm volatile("cp.async.wait_group 0;");
        }
        __syncthreads();

        const float* As = sm + (c & 1)*STAGE_F;
        const float* Ws = As + 128*KP;

        #pragma unroll
        for (int ks = 0; ks < KC/8; ++ks){
            const int cc = ks*8 + tig;
            unsigned af[2][4];
            #pragma unroll
            for (int mt = 0; mt < 2; mt++){
                int r = wm*32 + mt*16 + gid;
                af[mt][0] = __float_as_uint(As[r*KP + cc]);
                af[mt][1] = __float_as_uint(As[(r+8)*KP + cc]);
                af[mt][2] = __float_as_uint(As[r*KP + cc + 4]);
                af[mt][3] = __float_as_uint(As[(r+8)*KP + cc + 4]);
            }
            #pragma unroll
            for (int nt = 0; nt < 8; nt++){
                int n = wn*64 + nt*8 + gid;
                unsigned b0 = __float_as_uint(Ws[n*KP + cc]);
                unsigned b1 = __float_as_uint(Ws[n*KP + cc + 4]);
                mma_tf32(acc[0][nt], af[0], b0, b1);
                mma_tf32(acc[1][nt], af[1], b0, b1);
            }
        }
        __syncthreads();
    }

    #pragma unroll
    for (int mt = 0; mt < 2; mt++){
        size_t r = m0 + wm*32 + mt*16 + gid;
        #pragma unroll
        for (int nt = 0; nt < 8; nt++){
            int col = wn*64 + nt*8 + 2*tig;
            float bb0 = bs[col], bb1 = bs[col+1];
            *(float2*)(out + r*G_ + col)
                = make_float2(acc[mt][nt][0] + bb0, acc[mt][nt][1] + bb1);
            *(float2*)(out + (r+8)*G_ + col)
                = make_float2(acc[mt][nt][2] + bb0, acc[mt][nt][3] + bb1);
        }
    }
}

// ---------------------------------------------------------------- LSTM scan
// Tensor-core scan v3. Block = 512 thr = TWO independent 8-warp halves with
// NAMED barriers (bar.sync 1/2), each half = 8 seqs (R13 gate-type-per-N-
// tile mapping; cells register-local). Races fixed: wait_group BEFORE the
// barrier (barrier publishes all threads' cp.async data); triple-buffered
// pre staged at TOP of step t for t+2 into the buffer whose readers were
// barrier-separated one step ago. Incremental pointers (no per-step index
// math). Single 8-deep mma chain per gate type (4 independent chains).
#define SQ 8                      // sequences per half
#define PRP 264                   // padded row (floats) for pre
#define HRP 68                    // padded row for h
#define PSTB (SQ*PRP*4)           // stage stride in bytes

__global__ void __launch_bounds__(512,1)
lstm_scan(const float* __restrict__ pre, const float* __restrict__ w_hh,
          float* __restrict__ h_out)
{
    __shared__ __align__(16) float pre_s[2][3][SQ][PRP];  // [half][stage][seq]
    __shared__ __align__(16) float h_s[2][2][SQ][HRP];    // [half][buf][seq]

    const int tid  = threadIdx.x;
    const int hf   = tid >> 8;           // half 0/1
    const int ht   = tid & 255;
    const int warp = ht >> 5, lane = ht & 31;
    const int gid  = lane >> 2, tig = lane & 3;
    const int sbase = blockIdx.x * 2*SQ + hf*SQ;

    for (int i = tid; i < 2*2*SQ*HRP; i += 512) ((float*)h_s)[i] = 0.f;

    // B-fragments: nsub = gate type; gate = nsub*64 + warp*8 + gid
    unsigned bw[4][8][2];
    #pragma unroll
    for (int nsub = 0; nsub < 4; nsub++){
        int gate = nsub*64 + warp*8 + gid;
        #pragma unroll
        for (int ks = 0; ks < 8; ks++){
            bw[nsub][ks][0] = __float_as_uint(w_hh[gate*H_ + ks*8 + tig]);
            bw[nsub][ks][1] = __float_as_uint(w_hh[gate*H_ + ks*8 + tig + 4]);
        }
    }

    // staging: thread copies 2 cp16 (idx = ht, ht+256) -> (seq, seg)
    const int sq0 = ht >> 6,          sg0 = ht & 63;
    const int sq1 = (ht + 256) >> 6,  sg1 = (ht + 256) & 63;
    const float* p0r = pre + ((size_t)(sbase + sq0) * T_) * G_ + sg0*4;
    const float* p1r = pre + ((size_t)(sbase + sq1) * T_) * G_ + sg1*4;
    const unsigned d0 = smaddr(&pre_s[hf][0][sq0][sg0*4]);
    const unsigned d1 = smaddr(&pre_s[hf][0][sq1][sg1*4]);
    int tnext = 0;   // time currently addressed by p0r/p1r

    // cell state: seq gid, cells jc, jc+1
    const int jc = warp*8 + 2*tig;
    float c0 = 0.f, c1 = 0.f;
    float* hop = h_out + ((size_t)(sbase + gid) * T_) * H_ + jc;

    __syncthreads();

    // pre-stage times 0 and 1 (one commit each)
    #pragma unroll
    for (int s = 0; s < 2; s++){
        cp16(d0 + s*PSTB, p0r);
        cp16(d1 + s*PSTB, p1r);
        asm volatile("cp.async.commit_group;");
        if (tnext < T_-1){ p0r += G_; p1r += G_; tnext++; }
    }

    const int barid = 1 + hf;

    for (int t = 0; t < T_; ++t){
        const int rb = t & 1;
        const int sb = t % 3;              // buffer holding pre_t
        const int sn = (t + 2) % 3;        // buffer to refill (readers done)

        asm volatile("cp.async.wait_group 1;");
        asm volatile("bar.sync %0, 256;" :: "r"(barid) : "memory");

        // refill: stage pre_{t+2}
        cp16(d0 + sn*PSTB, p0r);
        cp16(d1 + sn*PSTB, p1r);
        asm volatile("cp.async.commit_group;");
        if (tnext < T_-1){ p0r += G_; p1r += G_; tnext++; }

        // gates = h @ W^T : 4 gate types, 8-deep chains
        float C[4][4];
        #pragma unroll
        for (int n = 0; n < 4; n++){
            C[n][0] = 0.f; C[n][1] = 0.f; C[n][2] = 0.f; C[n][3] = 0.f;
        }
        const float* hrow = h_s[hf][rb][gid];
        #pragma unroll
        for (int ks = 0; ks < 8; ks++){
            unsigned a[4];
            a[0] = __float_as_uint(hrow[ks*8 + tig]);
            a[1] = 0u;
            a[2] = __float_as_uint(hrow[ks*8 + tig + 4]);
            a[3] = 0u;
            #pragma unroll
            for (int nsub = 0; nsub < 4; nsub++)
                mma_tf32(C[nsub], a, bw[nsub][ks][0], bw[nsub][ks][1]);
        }

        // add pre, activate (nsub==2 tanh, else sigmoid via tanh identity)
        float vv[4][2];
        #pragma unroll
        for (int nsub = 0; nsub < 4; nsub++){
            float2 p = *(const float2*)&pre_s[hf][sb][gid][nsub*64 + jc];
            float x0 = C[nsub][0] + p.x;
            float x1 = C[nsub][1] + p.y;
            if (nsub == 2){
                vv[nsub][0] = tanh_fast(x0);
                vv[nsub][1] = tanh_fast(x1);
            } else {
                vv[nsub][0] = fmaf(tanh_fast(0.5f*x0), 0.5f, 0.5f);
                vv[nsub][1] = fmaf(tanh_fast(0.5f*x1), 0.5f, 0.5f);
            }
        }

        // cell update — register-local
        c0 = fmaf(vv[1][0], c0, vv[0][0] * vv[2][0]);
        c1 = fmaf(vv[1][1], c1, vv[0][1] * vv[2][1]);
        float h0v = vv[3][0] * tanh_fast(c0);
        float h1v = vv[3][1] * tanh_fast(c1);

        *(float2*)&h_s[hf][rb ^ 1][gid][jc] = make_float2(h0v, h1v);
        *(float2*)hop = make_float2(h0v, h1v);
        hop += H_;
    }
}

// ---------------------------------------------------------------- FC head
__global__ void fc_kernel(const float* __restrict__ h, const float* __restrict__ fw,
                          const float* __restrict__ fb, float* __restrict__ out)
{
    size_t m = (size_t)blockIdx.x * blockDim.x + threadIdx.x;
    const float4* hv = (const float4*)(h + m * H_);
    float acc = 0.f;
    #pragma unroll
    for (int i = 0; i < H_/4; i++){
        float4 a = hv[i];
        float4 w = __ldg(((const float4*)fw) + i);
        acc = fmaf(a.x, w.x, fmaf(a.y, w.y, fmaf(a.z, w.z, fmaf(a.w, w.w, acc))));
    }
    out[m] = acc + __ldg(fb);
}

// ---------------------------------------------------------------- launch
extern "C" void kernel_launch(void* const* d_in, const int* in_sizes, int n_in,
                              void* d_out, int out_size)
{
    const float* x     = (const float*)d_in[0];
    const float* w_ih0 = (const float*)d_in[1];
    const float* w_hh0 = (const float*)d_in[2];
    const float* b_ih0 = (const float*)d_in[3];
    const float* b_hh0 = (const float*)d_in[4];
    const float* w_ih1 = (const float*)d_in[5];
    const float* w_hh1 = (const float*)d_in[6];
    const float* b_ih1 = (const float*)d_in[7];
    const float* b_hh1 = (const float*)d_in[8];
    const float* w_ih2 = (const float*)d_in[9];
    const float* w_hh2 = (const float*)d_in[10];
    const float* b_ih2 = (const float*)d_in[11];
    const float* b_hh2 = (const float*)d_in[12];
    const float* fc_w  = (const float*)d_in[13];
    const float* fc_b  = (const float*)d_in[14];
    float* out = (float*)d_out;

    float *pre, *h0, *h1;
    cudaGetSymbolAddress((void**)&pre, g_pre);
    cudaGetSymbolAddress((void**)&h0,  g_h0);
    cudaGetSymbolAddress((void**)&h1,  g_h1);

    const int smemG = (2*STAGE_F + 256) * 4;
    cudaFuncSetAttribute(gemm_pre<128>, cudaFuncAttributeMaxDynamicSharedMemorySize, smemG);
    cudaFuncSetAttribute(gemm_pre<64>,  cudaFuncAttributeMaxDynamicSharedMemorySize, smemG);

    gemm_pre<128><<<M_/128, 512, smemG>>>(x,  w_ih0, b_ih0, b_hh0, pre);
    lstm_scan    <<<B_/(2*SQ), 512>>>(pre, w_hh0, h0);
    gemm_pre<64> <<<M_/128, 512, smemG>>>(h0, w_ih1, b_ih1, b_hh1, pre);
    lstm_scan    <<<B_/(2*SQ), 512>>>(pre, w_hh1, h1);
    gemm_pre<64> <<<M_/128, 512, smemG>>>(h1, w_ih2, b_ih2, b_hh2, pre);
    lstm_scan    <<<B_/(2*SQ), 512>>>(pre, w_hh2, h0);
    fc_kernel    <<<M_/256, 256>>>(h0, fc_w, fc_b, out);
}

// round 15
// speedup vs baseline: 1.6915x; 1.6524x over previous
#include <cuda_runtime.h>
#include <cstdint>
#include <cstddef>

#define B_ 256
#define T_ 2048
#define I_ 128
#define H_ 64
#define G_ 256          // 4*H
#define M_ (B_*T_)      // 524288

// Scratch (device globals: allocation-free rule)
__device__ float g_pre[(size_t)M_ * G_];   // 512 MB
__device__ float g_h0 [(size_t)M_ * H_];   // 128 MB
__device__ float g_h1 [(size_t)M_ * H_];   // 128 MB

// ---------------------------------------------------------------- helpers
__device__ __forceinline__ void mma_tf32(float c[4], const unsigned a[4],
                                         unsigned b0, unsigned b1){
    asm volatile("mma.sync.aligned.m16n8k8.row.col.f32.tf32.tf32.f32 "
        "{%0,%1,%2,%3},{%4,%5,%6,%7},{%8,%9},{%0,%1,%2,%3};"
        : "+f"(c[0]),"+f"(c[1]),"+f"(c[2]),"+f"(c[3])
        : "r"(a[0]),"r"(a[1]),"r"(a[2]),"r"(a[3]),"r"(b0),"r"(b1));
}

__device__ __forceinline__ float tanh_fast(float x){
    float y; asm("tanh.approx.f32 %0, %1;" : "=f"(y) : "f"(x)); return y;
}

__device__ __forceinline__ unsigned smaddr(const void* p){
    return (unsigned)__cvta_generic_to_shared(p);
}
__device__ __forceinline__ void cp16(unsigned dst, const void* src){
    asm volatile("cp.async.cg.shared.global [%0], [%1], 16;" :: "r"(dst), "l"(src));
}

// ---------------------------------------------------------------- pre-GEMM
// (R8 exact) 512 threads, BM=128, N=256, K chunked 32, cp.async dbl buffer.
#define KC 32
#define KP 36
#define STAGE_F (128*KP + 256*KP)

template<int K>
__global__ void __launch_bounds__(512,1)
gemm_pre(const float* __restrict__ A, const float* __restrict__ W,
         const float* __restrict__ b_ih, const float* __restrict__ b_hh,
         float* __restrict__ out)
{
    extern __shared__ float sm[];
    float* bs = sm + 2*STAGE_F;

    const int tid = threadIdx.x;
    const size_t m0 = (size_t)blockIdx.x * 128;

    if (tid < 256) bs[tid] = b_ih[tid] + b_hh[tid];

    auto copy_chunk = [&](int c, int st){
        float* Asd = sm + st*STAGE_F;
        float* Wsd = Asd + 128*KP;
        #pragma unroll
        for (int i = tid; i < 128*8; i += 512){
            int row = i >> 3, seg = i & 7;
            cp16(smaddr(Asd + row*KP + seg*4),
                 A + (m0 + row)*(size_t)K + c*KC + seg*4);
        }
        #pragma unroll
        for (int i = tid; i < 256*8; i += 512){
            int row = i >> 3, seg = i & 7;
            cp16(smaddr(Wsd + row*KP + seg*4),
                 W + (size_t)row*K + c*KC + seg*4);
        }
    };

    const int warp = tid >> 5, lane = tid & 31;
    const int wm = warp >> 2, wn = warp & 3;
    const int gid = lane >> 2, tig = lane & 3;

    float acc[2][8][4];
    #pragma unroll
    for (int a = 0; a < 2; a++)
        #pragma unroll
        for (int b = 0; b < 8; b++)
            #pragma unroll
            for (int d = 0; d < 4; d++) acc[a][b][d] = 0.f;

    constexpr int NCH = K / KC;

    copy_chunk(0, 0);
    asm volatile("cp.async.commit_group;");

    for (int c = 0; c < NCH; ++c){
        if (c + 1 < NCH){
            copy_chunk(c + 1, (c + 1) & 1);
            asm volatile("cp.async.commit_group;");
            asm volatile("cp.async.wait_group 1;");
        } else {
            asm volatile("cp.async.wait_group 0;");
        }
        __syncthreads();

        const float* As = sm + (c & 1)*STAGE_F;
        const float* Ws = As + 128*KP;

        #pragma unroll
        for (int ks = 0; ks < KC/8; ++ks){
            const int cc = ks*8 + tig;
            unsigned af[2][4];
            #pragma unroll
            for (int mt = 0; mt < 2; mt++){
                int r = wm*32 + mt*16 + gid;
                af[mt][0] = __float_as_uint(As[r*KP + cc]);
                af[mt][1] = __float_as_uint(As[(r+8)*KP + cc]);
                af[mt][2] = __float_as_uint(As[r*KP + cc + 4]);
                af[mt][3] = __float_as_uint(As[(r+8)*KP + cc + 4]);
            }
            #pragma unroll
            for (int nt = 0; nt < 8; nt++){
                int n = wn*64 + nt*8 + gid;
                unsigned b0 = __float_as_uint(Ws[n*KP + cc]);
                unsigned b1 = __float_as_uint(Ws[n*KP + cc + 4]);
                mma_tf32(acc[0][nt], af[0], b0, b1);
                mma_tf32(acc[1][nt], af[1], b0, b1);
            }
        }
        __syncthreads();
    }

    #pragma unroll
    for (int mt = 0; mt < 2; mt++){
        size_t r = m0 + wm*32 + mt*16 + gid;
        #pragma unroll
        for (int nt = 0; nt < 8; nt++){
            int col = wn*64 + nt*8 + 2*tig;
            float bb0 = bs[col], bb1 = bs[col+1];
            *(float2*)(out + r*G_ + col)
                = make_float2(acc[mt][nt][0] + bb0, acc[mt][nt][1] + bb1);
            *(float2*)(out + (r+8)*G_ + col)
                = make_float2(acc[mt][nt][2] + bb0, acc[mt][nt][3] + bb1);
        }
    }
}

// ---------------------------------------------------------------- LSTM scan
// (R10 structure + NAMED PER-HALF BARRIERS.) Block = TWO sequences in two
// independent 256-thread halves (warps 0-7 seq A, warps 8-15 seq B); each
// half: st = tid&255 -> (j = st>>2, gt = st&3), 4 gates of a cell in 4
// adjacent lanes, gate exchange via shfl, K-paired weights in 32 u64 regs,
// per-warp broadcast LDS of own h buffer, tanh.approx activations, ONE
// bar.sync(1+half, 256) per step — halves drift independently so their
// latency tails overlap. Grid 128 -> 1 block/SM.
__global__ void __launch_bounds__(512,1)
lstm_scan(const float* __restrict__ pre, const float* __restrict__ w_hh,
          float* __restrict__ h_out)
{
    __shared__ __align__(16) float h_s[2][2][H_];   // [buf][seq][j]

    const int tid = threadIdx.x;
    const int sh  = tid >> 8;          // seq half 0/1
    const int st  = tid & 255;         // thread-in-half
    const int j   = st >> 2;           // cell 0..63
    const int gt  = st & 3;            // 0=i 1=f 2=g 3=o
    const int grow = gt * H_ + j;      // row in w_hh / column in pre
    const int b   = blockIdx.x * 2 + sh;

    // activation: gt==2 -> tanh(a); else sigmoid(a) = 0.5*tanh(0.5a)+0.5
    const float am = (gt == 2) ? 1.f : 0.5f;

    if (tid < 2*2*H_) ((float*)h_s)[tid] = 0.f;

    // 32 K-paired weight u64: wpk[m] = {w[2m], w[2m+1]}
    unsigned long long wpk[32];
    {
        const float4* wr = (const float4*)(w_hh + grow*H_);
        #pragma unroll
        for (int k4 = 0; k4 < 16; k4++){
            float4 v = wr[k4];
            asm("mov.b64 %0,{%1,%2};" : "=l"(wpk[2*k4+0]) : "f"(v.x), "f"(v.y));
            asm("mov.b64 %0,{%1,%2};" : "=l"(wpk[2*k4+1]) : "f"(v.z), "f"(v.w));
        }
    }

    // pre pointer + distance-2 prefetch
    const float* pp = pre + ((size_t)b * T_) * G_ + grow;
    float p0 = pp[0];
    float p1 = pp[G_];

    float creg = 0.f;
    const unsigned lbase = (tid & 31) & ~3u;
    const float ab = (gt == 2) ? 0.f : 0.5f;
    const int barid = 1 + sh;

    __syncthreads();    // one-time block-wide: h_s zero-init published

    for (int t = 0; t < T_; ++t){
        int tp = (t + 2 < T_) ? t + 2 : T_ - 1;
        float pn = __ldg(pp + (size_t)tp * G_);

        const int rb = t & 1;
        unsigned long long a0, a1, a2, a3;
        asm("mov.b64 %0,{%1,%2};" : "=l"(a0) : "f"(p0),  "f"(0.f));
        asm("mov.b64 %0,{%1,%2};" : "=l"(a1) : "f"(0.f), "f"(0.f));
        asm("mov.b64 %0,{%1,%2};" : "=l"(a2) : "f"(0.f), "f"(0.f));
        asm("mov.b64 %0,{%1,%2};" : "=l"(a3) : "f"(0.f), "f"(0.f));

        const ulonglong2* hv = (const ulonglong2*)h_s[rb][sh];
        #pragma unroll
        for (int i = 0; i < 8; i++){
            ulonglong2 x = hv[i];
            ulonglong2 y = hv[i+8];
            asm("fma.rn.f32x2 %0, %1, %2, %0;" : "+l"(a0) : "l"(wpk[2*i+0]),  "l"(x.x));
            asm("fma.rn.f32x2 %0, %1, %2, %0;" : "+l"(a1) : "l"(wpk[2*i+1]),  "l"(x.y));
            asm("fma.rn.f32x2 %0, %1, %2, %0;" : "+l"(a2) : "l"(wpk[2*i+16]), "l"(y.x));
            asm("fma.rn.f32x2 %0, %1, %2, %0;" : "+l"(a3) : "l"(wpk[2*i+17]), "l"(y.y));
        }
        unsigned long long s01, s23, s;
        asm("add.rn.f32x2 %0, %1, %2;" : "=l"(s01) : "l"(a0), "l"(a1));
        asm("add.rn.f32x2 %0, %1, %2;" : "=l"(s23) : "l"(a2), "l"(a3));
        asm("add.rn.f32x2 %0, %1, %2;" : "=l"(s)   : "l"(s01), "l"(s23));
        float sl, shi;
        asm("mov.b64 {%0,%1}, %2;" : "=f"(sl), "=f"(shi) : "l"(s));
        float a = sl + shi;                        // gate pre-activation

        // activation via single MUFU tanh
        float v = fmaf(tanh_fast(a * am), am + ((gt==2)?0.f:0.f), ab);
        // (am doubles as output scale: 1 for tanh, 0.5 for sigmoid)

        float iv = __shfl_sync(0xffffffffu, v, lbase + 0, 32);
        float fv = __shfl_sync(0xffffffffu, v, lbase + 1, 32);
        float gv = __shfl_sync(0xffffffffu, v, lbase + 2, 32);
        float ov = __shfl_sync(0xffffffffu, v, lbase + 3, 32);

        creg = fmaf(fv, creg, iv * gv);
        float h = ov * tanh_fast(creg);

        if (gt == 0){
            h_s[rb ^ 1][sh][j] = h;
            h_out[((size_t)b * T_ + t) * H_ + j] = h;
        }
        p0 = p1; p1 = pn;
        asm volatile("bar.sync %0, 256;" :: "r"(barid) : "memory");
    }
}

// ---------------------------------------------------------------- FC head
__global__ void fc_kernel(const float* __restrict__ h, const float* __restrict__ fw,
                          const float* __restrict__ fb, float* __restrict__ out)
{
    size_t m = (size_t)blockIdx.x * blockDim.x + threadIdx.x;
    const float4* hv = (const float4*)(h + m * H_);
    float acc = 0.f;
    #pragma unroll
    for (int i = 0; i < H_/4; i++){
        float4 a = hv[i];
        float4 w = __ldg(((const float4*)fw) + i);
        acc = fmaf(a.x, w.x, fmaf(a.y, w.y, fmaf(a.z, w.z, fmaf(a.w, w.w, acc))));
    }
    out[m] = acc + __ldg(fb);
}

// ---------------------------------------------------------------- launch
extern "C" void kernel_launch(void* const* d_in, const int* in_sizes, int n_in,
                              void* d_out, int out_size)
{
    const float* x     = (const float*)d_in[0];
    const float* w_ih0 = (const float*)d_in[1];
    const float* w_hh0 = (const float*)d_in[2];
    const float* b_ih0 = (const float*)d_in[3];
    const float* b_hh0 = (const float*)d_in[4];
    const float* w_ih1 = (const float*)d_in[5];
    const float* w_hh1 = (const float*)d_in[6];
    const float* b_ih1 = (const float*)d_in[7];
    const float* b_hh1 = (const float*)d_in[8];
    const float* w_ih2 = (const float*)d_in[9];
    const float* w_hh2 = (const float*)d_in[10];
    const float* b_ih2 = (const float*)d_in[11];
    const float* b_hh2 = (const float*)d_in[12];
    const float* fc_w  = (const float*)d_in[13];
    const float* fc_b  = (const float*)d_in[14];
    float* out = (float*)d_out;

    float *pre, *h0, *h1;
    cudaGetSymbolAddress((void**)&pre, g_pre);
    cudaGetSymbolAddress((void**)&h0,  g_h0);
    cudaGetSymbolAddress((void**)&h1,  g_h1);

    const int smemG = (2*STAGE_F + 256) * 4;
    cudaFuncSetAttribute(gemm_pre<128>, cudaFuncAttributeMaxDynamicSharedMemorySize, smemG);
    cudaFuncSetAttribute(gemm_pre<64>,  cudaFuncAttributeMaxDynamicSharedMemorySize, smemG);

    gemm_pre<128><<<M_/128, 512, smemG>>>(x,  w_ih0, b_ih0, b_hh0, pre);
    lstm_scan    <<<B_/2,   512>>>(pre, w_hh0, h0);
    gemm_pre<64> <<<M_/128, 512, smemG>>>(h0, w_ih1, b_ih1, b_hh1, pre);
    lstm_scan    <<<B_/2,   512>>>(pre, w_hh1, h1);
    gemm_pre<64> <<<M_/128, 512, smemG>>>(h1, w_ih2, b_ih2, b_hh2, pre);
    lstm_scan    <<<B_/2,   512>>>(pre, w_hh2, h0);
    fc_kernel    <<<M_/256, 256>>>(h0, fc_w, fc_b, out);
}